// round 6
// baseline (speedup 1.0000x reference)
#include <cuda_runtime.h>
#include <cuda_bf16.h>
#include <cstdint>

// Problem: B=32, T=32, L=196, S=512, D=512
// Math reduction: softmax is shift-invariant => attention independent of h,t.
//   attn[b,:]  = softmax_l( x_static[b] @ (W1@V) )
//   ctx[b,:]   = attn[b,:] @ x_static[b]
//   out[b,t,:] = concat(x[b,t,:], ctx[b,:]) @ W3 + b3   (K=1024 tensor-core GEMM)

#define D_ 512
#define S_ 512
#define L_ 196
#define B_ 32
#define T_ 32

__device__ float g_w1v[S_];
__device__ float g_scores[B_ * L_];
__device__ float g_ctx[B_ * S_];

__device__ __forceinline__ uint32_t f2tf32(float f) {
    uint32_t u;
    asm("cvt.rna.tf32.f32 %0, %1;" : "=r"(u) : "f"(f));
    return u;
}

// ---------------------------------------------------------------------------
// Kernel 1: w1v[s] = dot(W1[s,:], V). warp per row, float4.
// ---------------------------------------------------------------------------
__global__ __launch_bounds__(256) void w1v_kernel(const float* __restrict__ W1,
                                                  const float* __restrict__ V) {
    int gwarp = (blockIdx.x * blockDim.x + threadIdx.x) >> 5;
    int lane = threadIdx.x & 31;
    if (gwarp >= S_) return;
    const float4* row = (const float4*)(W1 + (size_t)gwarp * D_);
    const float4* v4 = (const float4*)V;
    float acc = 0.0f;
#pragma unroll
    for (int i = 0; i < 4; i++) {
        int idx = lane + i * 32;
        float4 a = row[idx];
        float4 b = v4[idx];
        acc += a.x * b.x + a.y * b.y + a.z * b.z + a.w * b.w;
    }
#pragma unroll
    for (int o = 16; o; o >>= 1) acc += __shfl_xor_sync(0xffffffffu, acc, o);
    if (lane == 0) g_w1v[gwarp] = acc;
}

// ---------------------------------------------------------------------------
// Kernel 2: scores[b,l] = dot(x_static[b,l,:], w1v). grid (7, 32), warp/row.
// ---------------------------------------------------------------------------
__global__ __launch_bounds__(256) void scores_kernel(const float* __restrict__ xs) {
    int b = blockIdx.y;
    int l0 = blockIdx.x * 28;
    __shared__ float sw1v[S_];
    int tid = threadIdx.x;
    if (tid < S_ / 4) ((float4*)sw1v)[tid] = ((const float4*)g_w1v)[tid];
    __syncthreads();

    int warp = tid >> 5, lane = tid & 31;
    const float* X = xs + (size_t)b * L_ * S_;
    for (int r = warp; r < 28; r += 8) {
        int l = l0 + r;
        const float4* row = (const float4*)(X + (size_t)l * S_);
        const float4* w4 = (const float4*)sw1v;
        float acc = 0.0f;
#pragma unroll
        for (int i = 0; i < 4; i++) {
            int idx = lane + i * 32;
            float4 a = row[idx];
            float4 w = w4[idx];
            acc += a.x * w.x + a.y * w.y + a.z * w.z + a.w * w.w;
        }
#pragma unroll
        for (int o = 16; o; o >>= 1) acc += __shfl_xor_sync(0xffffffffu, acc, o);
        if (lane == 0) g_scores[b * L_ + l] = acc;
    }
}

// ---------------------------------------------------------------------------
// Kernel 3: softmax (recomputed per block) + ctx.
// grid (4, 32): s-chunk of 128, batch b. block 128.
// ---------------------------------------------------------------------------
__global__ __launch_bounds__(128) void ctx_kernel(const float* __restrict__ xs) {
    int b = blockIdx.y;
    int s = blockIdx.x * 128 + threadIdx.x;
    __shared__ float sc[L_];
    __shared__ float red[4];
    __shared__ float s_max, s_sum;
    int tid = threadIdx.x;
    int warp = tid >> 5, lane = tid & 31;

    float v0 = g_scores[b * L_ + tid];
    float v1 = (tid + 128 < L_) ? g_scores[b * L_ + tid + 128] : -1e30f;

    float m = fmaxf(v0, v1);
#pragma unroll
    for (int o = 16; o; o >>= 1) m = fmaxf(m, __shfl_xor_sync(0xffffffffu, m, o));
    if (lane == 0) red[warp] = m;
    __syncthreads();
    if (tid == 0) s_max = fmaxf(fmaxf(red[0], red[1]), fmaxf(red[2], red[3]));
    __syncthreads();
    float mx = s_max;

    float e0 = __expf(v0 - mx);
    float e1 = (tid + 128 < L_) ? __expf(v1 - mx) : 0.0f;
    float ps = e0 + e1;
#pragma unroll
    for (int o = 16; o; o >>= 1) ps += __shfl_xor_sync(0xffffffffu, ps, o);
    if (lane == 0) red[warp] = ps;
    __syncthreads();
    if (tid == 0) s_sum = red[0] + red[1] + red[2] + red[3];
    __syncthreads();
    float inv = 1.0f / s_sum;
    sc[tid] = e0 * inv;
    if (tid + 128 < L_) sc[tid + 128] = e1 * inv;
    __syncthreads();

    const float* Xp = xs + (size_t)b * L_ * S_ + s;
    float acc = 0.0f;
#pragma unroll 4
    for (int l = 0; l < L_; l++) acc += sc[l] * Xp[(size_t)l * S_];
    g_ctx[b * S_ + s] = acc;
}

// ---------------------------------------------------------------------------
// Kernel 4: TF32 tensor-core GEMM with concat-K.
//   out[b*32+t, n] = sum_{k<512} x[b,t,k]*W3[k,n]
//                  + sum_{k>=512} ctx[b,k-512]*W3[k,n] + b3[n]
// BM=32 (one batch), BN=64, BK=32, K=1024. 128 threads = 4 warps.
// warp (mhalf = w&1, nhalf = w>>1); mma.sync m16n8k8 tf32.
// As stride 36, Bs stride 72 -> all fragment LDS conflict-free.
// ---------------------------------------------------------------------------
__global__ __launch_bounds__(128) void out_gemm_tf32(const float* __restrict__ x,
                                                     const float* __restrict__ W3,
                                                     const float* __restrict__ b3,
                                                     float* __restrict__ out) {
    __shared__ uint32_t As[32][36];
    __shared__ uint32_t Bs[32][72];

    int tid = threadIdx.x;
    int w = tid >> 5, lane = tid & 31;
    int b = blockIdx.y;
    int n0 = blockIdx.x * 64;

    int m_base = (w & 1) * 16;
    int n_base = (w >> 1) * 32;
    int r = lane >> 2;
    int c = lane & 3;

    float d[4][4];
#pragma unroll
    for (int i = 0; i < 4; i++)
#pragma unroll
        for (int j = 0; j < 4; j++) d[i][j] = 0.0f;

    for (int k0 = 0; k0 < 1024; k0 += 32) {
        // ---- A tile [32 rows][32 k] ----
        if (k0 < 512) {
#pragma unroll
            for (int it = 0; it < 2; it++) {
                int slot = tid + it * 128;   // 256 float4 slots
                int row = slot >> 3;
                int c4 = slot & 7;
                float4 v = *(const float4*)(x + ((size_t)b * T_ + row) * D_ + k0 + c4 * 4);
                uint32_t* dst = &As[row][c4 * 4];
                dst[0] = f2tf32(v.x);
                dst[1] = f2tf32(v.y);
                dst[2] = f2tf32(v.z);
                dst[3] = f2tf32(v.w);
            }
        } else {
            int kk = tid & 31;
            uint32_t tv = f2tf32(g_ctx[b * S_ + (k0 - 512) + kk]);
            int rbase = (tid >> 5) * 8;
#pragma unroll
            for (int i = 0; i < 8; i++) As[rbase + i][kk] = tv;
        }
        // ---- B tile [32 k][64 n] ----
#pragma unroll
        for (int it = 0; it < 4; it++) {
            int slot = tid + it * 128;       // 512 float4 slots
            int k = slot >> 4;
            int n4 = slot & 15;
            float4 v = *(const float4*)(W3 + (size_t)(k0 + k) * D_ + n0 + n4 * 4);
            uint4 u;
            u.x = f2tf32(v.x);
            u.y = f2tf32(v.y);
            u.z = f2tf32(v.z);
            u.w = f2tf32(v.w);
            *(uint4*)&Bs[k][n4 * 4] = u;
        }
        __syncthreads();

#pragma unroll
        for (int kk8 = 0; kk8 < 4; kk8++) {
            int kb = kk8 * 8;
            uint32_t a0 = As[m_base + r][kb + c];
            uint32_t a1 = As[m_base + r + 8][kb + c];
            uint32_t a2 = As[m_base + r][kb + c + 4];
            uint32_t a3 = As[m_base + r + 8][kb + c + 4];
            int kbl = kb + c;                 // B row for b0 (k = lane&3)
#pragma unroll
            for (int nt = 0; nt < 4; nt++) {
                int n = n_base + nt * 8 + r;  // B col (n = lane>>2)
                uint32_t b0 = Bs[kbl][n];
                uint32_t b1 = Bs[kbl + 4][n];
                asm volatile(
                    "mma.sync.aligned.m16n8k8.row.col.f32.tf32.tf32.f32 "
                    "{%0,%1,%2,%3}, {%4,%5,%6,%7}, {%8,%9}, {%0,%1,%2,%3};\n"
                    : "+f"(d[nt][0]), "+f"(d[nt][1]), "+f"(d[nt][2]), "+f"(d[nt][3])
                    : "r"(a0), "r"(a1), "r"(a2), "r"(a3), "r"(b0), "r"(b1));
            }
        }
        __syncthreads();
    }

    // epilogue: += b3, write out
    int gm0 = b * T_ + m_base;
    int gn0 = n0 + n_base;
    int c2 = c * 2;
#pragma unroll
    for (int nt = 0; nt < 4; nt++) {
        int n = gn0 + nt * 8 + c2;
        float2 bias = *(const float2*)(b3 + n);
        float2 o0, o1;
        o0.x = d[nt][0] + bias.x;
        o0.y = d[nt][1] + bias.y;
        o1.x = d[nt][2] + bias.x;
        o1.y = d[nt][3] + bias.y;
        *(float2*)(out + (size_t)(gm0 + r) * D_ + n) = o0;
        *(float2*)(out + (size_t)(gm0 + r + 8) * D_ + n) = o1;
    }
}

extern "C" void kernel_launch(void* const* d_in, const int* in_sizes, int n_in,
                              void* d_out, int out_size) {
    const float* x  = (const float*)d_in[0];   // [32,32,512]
    const float* xs = (const float*)d_in[1];   // [32,196,512]
    const float* W1 = (const float*)d_in[3];   // [512,512]
    const float* W3 = (const float*)d_in[5];   // [1024,512]
    const float* b3 = (const float*)d_in[7];   // [512]
    const float* V  = (const float*)d_in[8];   // [512,1]
    float* out = (float*)d_out;                // [32,32,512]

    w1v_kernel<<<64, 256>>>(W1, V);
    scores_kernel<<<dim3(7, B_), 256>>>(xs);
    ctx_kernel<<<dim3(4, B_), 128>>>(xs);
    out_gemm_tf32<<<dim3(D_ / 64, B_), 128>>>(x, W3, b3, out);
}

// round 9
// speedup vs baseline: 1.2014x; 1.2014x over previous
#include <cuda_runtime.h>
#include <cuda_bf16.h>
#include <cstdint>

// Problem: B=32, T=32, L=196, S=512, D=512
// Math reduction: softmax is shift-invariant => attention independent of h,t.
//   attn[b,:]  = softmax_l( x_static[b] @ (W1@V) )
//   ctx[b,:]   = attn[b,:] @ x_static[b]
//   out[b,t,:] = concat(x[b,t,:], ctx[b,:]) @ W3 + b3   (K=1024 TF32 MMA GEMM)

#define D_ 512
#define S_ 512
#define L_ 196
#define B_ 32
#define T_ 32
#define KTOT 1024
#define M_ 1024

__device__ float g_w1v[S_];
__device__ float g_scores[B_ * L_];
__device__ uint32_t g_A32[M_ * KTOT];    // tf32 concat(x, ctx-broadcast)
__device__ uint32_t g_W332[KTOT * D_];   // tf32 W3

__device__ __forceinline__ uint32_t f2tf32(float f) {
    uint32_t u;
    asm("cvt.rna.tf32.f32 %0, %1;" : "=r"(u) : "f"(f));
    return u;
}
__device__ __forceinline__ void cp_async16(uint32_t smem_addr, const void* gptr) {
    asm volatile("cp.async.cg.shared.global [%0], [%1], 16;\n" ::"r"(smem_addr),
                 "l"(gptr));
}
__device__ __forceinline__ void cp_commit() {
    asm volatile("cp.async.commit_group;\n");
}
template <int N>
__device__ __forceinline__ void cp_wait() {
    asm volatile("cp.async.wait_group %0;\n" ::"n"(N));
}

// ---------------------------------------------------------------------------
// Kernel 0: convert x -> g_A32[:, :512], W3 -> g_W332. Grid-stride float4.
// ---------------------------------------------------------------------------
__global__ __launch_bounds__(256) void prep_convert(const float* __restrict__ x,
                                                    const float* __restrict__ W3) {
    int gtid = blockIdx.x * 256 + threadIdx.x;  // 65536 threads
    // x: 131072 float4 slots
#pragma unroll
    for (int it = 0; it < 2; it++) {
        int i = gtid + it * 65536;
        int j = i * 4;                 // float index
        int m = j >> 9, k = j & 511;
        float4 v = *(const float4*)(x + j);
        uint4 u;
        u.x = f2tf32(v.x);
        u.y = f2tf32(v.y);
        u.z = f2tf32(v.z);
        u.w = f2tf32(v.w);
        *(uint4*)(g_A32 + (size_t)m * KTOT + k) = u;
    }
    // W3: 131072 float4 slots, same layout
#pragma unroll
    for (int it = 0; it < 2; it++) {
        int i = gtid + it * 65536;
        int j = i * 4;
        float4 v = *(const float4*)(W3 + j);
        uint4 u;
        u.x = f2tf32(v.x);
        u.y = f2tf32(v.y);
        u.z = f2tf32(v.z);
        u.w = f2tf32(v.w);
        *(uint4*)(g_W332 + j) = u;
    }
}

// ---------------------------------------------------------------------------
// Kernel 1: w1v[s] = dot(W1[s,:], V). warp per row, float4.
// ---------------------------------------------------------------------------
__global__ __launch_bounds__(256) void w1v_kernel(const float* __restrict__ W1,
                                                  const float* __restrict__ V) {
    int gwarp = (blockIdx.x * blockDim.x + threadIdx.x) >> 5;
    int lane = threadIdx.x & 31;
    if (gwarp >= S_) return;
    const float4* row = (const float4*)(W1 + (size_t)gwarp * D_);
    const float4* v4 = (const float4*)V;
    float acc = 0.0f;
#pragma unroll
    for (int i = 0; i < 4; i++) {
        int idx = lane + i * 32;
        float4 a = row[idx];
        float4 b = v4[idx];
        acc += a.x * b.x + a.y * b.y + a.z * b.z + a.w * b.w;
    }
#pragma unroll
    for (int o = 16; o; o >>= 1) acc += __shfl_xor_sync(0xffffffffu, acc, o);
    if (lane == 0) g_w1v[gwarp] = acc;
}

// ---------------------------------------------------------------------------
// Kernel 2: scores[b,l] = dot(x_static[b,l,:], w1v). grid (7, 32), warp/row.
// ---------------------------------------------------------------------------
__global__ __launch_bounds__(256) void scores_kernel(const float* __restrict__ xs) {
    int b = blockIdx.y;
    int l0 = blockIdx.x * 28;
    __shared__ float sw1v[S_];
    int tid = threadIdx.x;
    if (tid < S_ / 4) ((float4*)sw1v)[tid] = ((const float4*)g_w1v)[tid];
    __syncthreads();

    int warp = tid >> 5, lane = tid & 31;
    const float* X = xs + (size_t)b * L_ * S_;
    for (int r = warp; r < 28; r += 8) {
        int l = l0 + r;
        const float4* row = (const float4*)(X + (size_t)l * S_);
        const float4* w4 = (const float4*)sw1v;
        float acc = 0.0f;
#pragma unroll
        for (int i = 0; i < 4; i++) {
            int idx = lane + i * 32;
            float4 a = row[idx];
            float4 w = w4[idx];
            acc += a.x * w.x + a.y * w.y + a.z * w.z + a.w * w.w;
        }
#pragma unroll
        for (int o = 16; o; o >>= 1) acc += __shfl_xor_sync(0xffffffffu, acc, o);
        if (lane == 0) g_scores[b * L_ + l] = acc;
    }
}

// ---------------------------------------------------------------------------
// Kernel 3: softmax + ctx; writes tf32 broadcast into g_A32[:, 512:].
// grid (4, 32): s-chunk of 128, batch b. block 128.
// ---------------------------------------------------------------------------
__global__ __launch_bounds__(128) void ctx_kernel(const float* __restrict__ xs) {
    int b = blockIdx.y;
    int s = blockIdx.x * 128 + threadIdx.x;
    __shared__ float sc[L_];
    __shared__ float red[4];
    __shared__ float s_max, s_sum;
    int tid = threadIdx.x;
    int warp = tid >> 5, lane = tid & 31;

    float v0 = g_scores[b * L_ + tid];
    float v1 = (tid + 128 < L_) ? g_scores[b * L_ + tid + 128] : -1e30f;

    float m = fmaxf(v0, v1);
#pragma unroll
    for (int o = 16; o; o >>= 1) m = fmaxf(m, __shfl_xor_sync(0xffffffffu, m, o));
    if (lane == 0) red[warp] = m;
    __syncthreads();
    if (tid == 0) s_max = fmaxf(fmaxf(red[0], red[1]), fmaxf(red[2], red[3]));
    __syncthreads();
    float mx = s_max;

    float e0 = __expf(v0 - mx);
    float e1 = (tid + 128 < L_) ? __expf(v1 - mx) : 0.0f;
    float ps = e0 + e1;
#pragma unroll
    for (int o = 16; o; o >>= 1) ps += __shfl_xor_sync(0xffffffffu, ps, o);
    if (lane == 0) red[warp] = ps;
    __syncthreads();
    if (tid == 0) s_sum = red[0] + red[1] + red[2] + red[3];
    __syncthreads();
    float inv = 1.0f / s_sum;
    sc[tid] = e0 * inv;
    if (tid + 128 < L_) sc[tid + 128] = e1 * inv;
    __syncthreads();

    const float* Xp = xs + (size_t)b * L_ * S_ + s;
    float acc = 0.0f;
#pragma unroll 4
    for (int l = 0; l < L_; l++) acc += sc[l] * Xp[(size_t)l * S_];

    uint32_t tv = f2tf32(acc);
    size_t base = (size_t)(b * T_) * KTOT + 512 + s;
#pragma unroll
    for (int t = 0; t < T_; t++) g_A32[base + (size_t)t * KTOT] = tv;
}

// ---------------------------------------------------------------------------
// Kernel 4: TF32 MMA GEMM. out[m,n] = sum_k A32[m,k]*W332[k,n] + b3[n]
// M=1024, N=512, K=1024. BM=64, BN=64, BK=32. 128 threads = 4 warps,
// warp tile 32x32 (2 m-frags x 4 n-frags of m16n8k8). cp.async double buffer.
// ---------------------------------------------------------------------------
#define GBM 64
#define GBN 64
#define GBK 32

__global__ __launch_bounds__(128) void gemm_tc(const float* __restrict__ b3,
                                               float* __restrict__ out) {
    __shared__ uint32_t As[2][GBM][36];
    __shared__ uint32_t Bs[2][GBK][72];

    int tid = threadIdx.x;
    int w = tid >> 5, lane = tid & 31;
    int m0 = blockIdx.y * GBM, n0 = blockIdx.x * GBN;
    int m_warp = (w & 1) * 32;
    int n_warp = (w >> 1) * 32;
    int r = lane >> 2;
    int c = lane & 3;

    float d[2][4][4];
#pragma unroll
    for (int f = 0; f < 2; f++)
#pragma unroll
        for (int g = 0; g < 4; g++)
#pragma unroll
            for (int i = 0; i < 4; i++) d[f][g][i] = 0.0f;

    // per-thread load slots (4 for A, 4 for B)
    int arow[4], ac4[4], bk[4], bn4[4];
#pragma unroll
    for (int it = 0; it < 4; it++) {
        int slot = tid + it * 128;
        arow[it] = slot >> 3;          // 0..63
        ac4[it] = slot & 7;            // 0..7
        bk[it] = slot >> 4;            // 0..31
        bn4[it] = slot & 15;           // 0..15
    }

    auto issue_tile = [&](int k0, int buf) {
#pragma unroll
        for (int it = 0; it < 4; it++) {
            uint32_t dst = (uint32_t)__cvta_generic_to_shared(&As[buf][arow[it]][ac4[it] * 4]);
            cp_async16(dst, g_A32 + (size_t)(m0 + arow[it]) * KTOT + k0 + ac4[it] * 4);
        }
#pragma unroll
        for (int it = 0; it < 4; it++) {
            uint32_t dst = (uint32_t)__cvta_generic_to_shared(&Bs[buf][bk[it]][bn4[it] * 4]);
            cp_async16(dst, g_W332 + (size_t)(k0 + bk[it]) * D_ + n0 + bn4[it] * 4);
        }
        cp_commit();
    };

    issue_tile(0, 0);

    for (int t = 0; t < KTOT / GBK; t++) {
        int buf = t & 1;
        if (t + 1 < KTOT / GBK) {
            issue_tile((t + 1) * GBK, buf ^ 1);
            cp_wait<1>();
        } else {
            cp_wait<0>();
        }
        __syncthreads();

#pragma unroll
        for (int kk8 = 0; kk8 < 4; kk8++) {
            int kb = kk8 * 8;
            uint32_t a[2][4];
#pragma unroll
            for (int f = 0; f < 2; f++) {
                int mrow = m_warp + f * 16 + r;
                a[f][0] = As[buf][mrow][kb + c];
                a[f][1] = As[buf][mrow + 8][kb + c];
                a[f][2] = As[buf][mrow][kb + c + 4];
                a[f][3] = As[buf][mrow + 8][kb + c + 4];
            }
#pragma unroll
            for (int g = 0; g < 4; g++) {
                int ncol = n_warp + g * 8 + r;
                uint32_t b0 = Bs[buf][kb + c][ncol];
                uint32_t b1 = Bs[buf][kb + c + 4][ncol];
#pragma unroll
                for (int f = 0; f < 2; f++) {
                    asm volatile(
                        "mma.sync.aligned.m16n8k8.row.col.f32.tf32.tf32.f32 "
                        "{%0,%1,%2,%3}, {%4,%5,%6,%7}, {%8,%9}, {%0,%1,%2,%3};\n"
                        : "+f"(d[f][g][0]), "+f"(d[f][g][1]), "+f"(d[f][g][2]),
                          "+f"(d[f][g][3])
                        : "r"(a[f][0]), "r"(a[f][1]), "r"(a[f][2]), "r"(a[f][3]),
                          "r"(b0), "r"(b1));
                }
            }
        }
        __syncthreads();
    }

    // epilogue
    int c2 = c * 2;
#pragma unroll
    for (int g = 0; g < 4; g++) {
        int n = n0 + n_warp + g * 8 + c2;
        float2 bias = *(const float2*)(b3 + n);
#pragma unroll
        for (int f = 0; f < 2; f++) {
            int m = m0 + m_warp + f * 16 + r;
            float2 o0, o1;
            o0.x = d[f][g][0] + bias.x;
            o0.y = d[f][g][1] + bias.y;
            o1.x = d[f][g][2] + bias.x;
            o1.y = d[f][g][3] + bias.y;
            *(float2*)(out + (size_t)m * D_ + n) = o0;
            *(float2*)(out + (size_t)(m + 8) * D_ + n) = o1;
        }
    }
}

extern "C" void kernel_launch(void* const* d_in, const int* in_sizes, int n_in,
                              void* d_out, int out_size) {
    const float* x  = (const float*)d_in[0];   // [32,32,512]
    const float* xs = (const float*)d_in[1];   // [32,196,512]
    const float* W1 = (const float*)d_in[3];   // [512,512]
    const float* W3 = (const float*)d_in[5];   // [1024,512]
    const float* b3 = (const float*)d_in[7];   // [512]
    const float* V  = (const float*)d_in[8];   // [512,1]
    float* out = (float*)d_out;                // [32,32,512]

    prep_convert<<<256, 256>>>(x, W3);
    w1v_kernel<<<64, 256>>>(W1, V);
    scores_kernel<<<dim3(7, B_), 256>>>(xs);
    ctx_kernel<<<dim3(4, B_), 128>>>(xs);
    gemm_tc<<<dim3(D_ / GBN, M_ / GBM), 128>>>(b3, out);
}

// round 10
// speedup vs baseline: 1.4971x; 1.2461x over previous
#include <cuda_runtime.h>
#include <cuda_bf16.h>
#include <cstdint>

// Problem: B=32, T=32, L=196, S=512, D=512
// Math reduction: softmax is shift-invariant => attention independent of h,t.
//   attn[b,:]  = softmax_l( x_static[b] @ (W1@V) )
//   ctx[b,:]   = attn[b,:] @ x_static[b]
//   out[b,t,:] = concat(x[b,t,:], ctx[b,:]) @ W3 + b3   (K=1024 TF32 MMA GEMM)

#define D_ 512
#define S_ 512
#define L_ 196
#define B_ 32
#define T_ 32
#define KTOT 1024
#define M_ 1024
#define LCH 7
#define LPC 28

__device__ float g_w1v[S_];
__device__ float g_scores[B_ * L_];
__device__ float g_attn[B_ * L_];
__device__ float g_ctxpart[LCH][B_][S_];
__device__ uint32_t g_Ax32[M_ * D_];     // tf32 x
__device__ uint32_t g_ctx32[B_ * S_];    // tf32 ctx (compact)
__device__ uint32_t g_W332[KTOT * D_];   // tf32 W3

__device__ __forceinline__ uint32_t f2tf32(float f) {
    uint32_t u;
    asm("cvt.rna.tf32.f32 %0, %1;" : "=r"(u) : "f"(f));
    return u;
}
__device__ __forceinline__ void cp_async16(uint32_t smem_addr, const void* gptr) {
    asm volatile("cp.async.cg.shared.global [%0], [%1], 16;\n" ::"r"(smem_addr),
                 "l"(gptr));
}
__device__ __forceinline__ void cp_commit() {
    asm volatile("cp.async.commit_group;\n");
}
template <int N>
__device__ __forceinline__ void cp_wait() {
    asm volatile("cp.async.wait_group %0;\n" ::"n"(N));
}

// ---------------------------------------------------------------------------
// Kernel 0: convert x -> g_Ax32, W3 -> g_W332. Grid-stride float4.
// ---------------------------------------------------------------------------
__global__ __launch_bounds__(256) void prep_convert(const float* __restrict__ x,
                                                    const float* __restrict__ W3) {
    int gtid = blockIdx.x * 256 + threadIdx.x;  // 65536 threads
#pragma unroll
    for (int it = 0; it < 2; it++) {
        int j = (gtid + it * 65536) * 4;
        float4 v = *(const float4*)(x + j);
        uint4 u;
        u.x = f2tf32(v.x);
        u.y = f2tf32(v.y);
        u.z = f2tf32(v.z);
        u.w = f2tf32(v.w);
        *(uint4*)(g_Ax32 + j) = u;
    }
#pragma unroll
    for (int it = 0; it < 2; it++) {
        int j = (gtid + it * 65536) * 4;
        float4 v = *(const float4*)(W3 + j);
        uint4 u;
        u.x = f2tf32(v.x);
        u.y = f2tf32(v.y);
        u.z = f2tf32(v.z);
        u.w = f2tf32(v.w);
        *(uint4*)(g_W332 + j) = u;
    }
}

// ---------------------------------------------------------------------------
// Kernel 1: w1v[s] = dot(W1[s,:], V). warp per row, float4.
// ---------------------------------------------------------------------------
__global__ __launch_bounds__(256) void w1v_kernel(const float* __restrict__ W1,
                                                  const float* __restrict__ V) {
    int gwarp = (blockIdx.x * blockDim.x + threadIdx.x) >> 5;
    int lane = threadIdx.x & 31;
    if (gwarp >= S_) return;
    const float4* row = (const float4*)(W1 + (size_t)gwarp * D_);
    const float4* v4 = (const float4*)V;
    float acc = 0.0f;
#pragma unroll
    for (int i = 0; i < 4; i++) {
        int idx = lane + i * 32;
        float4 a = row[idx];
        float4 b = v4[idx];
        acc += a.x * b.x + a.y * b.y + a.z * b.z + a.w * b.w;
    }
#pragma unroll
    for (int o = 16; o; o >>= 1) acc += __shfl_xor_sync(0xffffffffu, acc, o);
    if (lane == 0) g_w1v[gwarp] = acc;
}

// ---------------------------------------------------------------------------
// Kernel 2: scores[b,l] = dot(x_static[b,l,:], w1v). grid (7, 32), warp/row.
// ---------------------------------------------------------------------------
__global__ __launch_bounds__(256) void scores_kernel(const float* __restrict__ xs) {
    int b = blockIdx.y;
    int l0 = blockIdx.x * LPC;
    __shared__ float sw1v[S_];
    int tid = threadIdx.x;
    if (tid < S_ / 4) ((float4*)sw1v)[tid] = ((const float4*)g_w1v)[tid];
    __syncthreads();

    int warp = tid >> 5, lane = tid & 31;
    const float* X = xs + (size_t)b * L_ * S_;
    for (int r = warp; r < LPC; r += 8) {
        int l = l0 + r;
        const float4* row = (const float4*)(X + (size_t)l * S_);
        const float4* w4 = (const float4*)sw1v;
        float acc = 0.0f;
#pragma unroll
        for (int i = 0; i < 4; i++) {
            int idx = lane + i * 32;
            float4 a = row[idx];
            float4 w = w4[idx];
            acc += a.x * w.x + a.y * w.y + a.z * w.z + a.w * w.w;
        }
#pragma unroll
        for (int o = 16; o; o >>= 1) acc += __shfl_xor_sync(0xffffffffu, acc, o);
        if (lane == 0) g_scores[b * L_ + l] = acc;
    }
}

// ---------------------------------------------------------------------------
// Kernel 3: softmax over l: g_attn[b,l] = exp(sc-max)/sum. grid 32, block 256.
// ---------------------------------------------------------------------------
__global__ __launch_bounds__(256) void softmax_kernel() {
    int b = blockIdx.x;
    int tid = threadIdx.x;
    int warp = tid >> 5, lane = tid & 31;
    __shared__ float red[8];
    __shared__ float s_max, s_sum;

    float v = (tid < L_) ? g_scores[b * L_ + tid] : -1e30f;
    float m = v;
#pragma unroll
    for (int o = 16; o; o >>= 1) m = fmaxf(m, __shfl_xor_sync(0xffffffffu, m, o));
    if (lane == 0) red[warp] = m;
    __syncthreads();
    if (warp == 0) {
        float t = (lane < 8) ? red[lane] : -1e30f;
#pragma unroll
        for (int o = 4; o; o >>= 1) t = fmaxf(t, __shfl_xor_sync(0xffffffffu, t, o));
        if (lane == 0) s_max = t;
    }
    __syncthreads();
    float e = (tid < L_) ? __expf(v - s_max) : 0.0f;
    float ps = e;
#pragma unroll
    for (int o = 16; o; o >>= 1) ps += __shfl_xor_sync(0xffffffffu, ps, o);
    if (lane == 0) red[warp] = ps;
    __syncthreads();
    if (warp == 0) {
        float t = (lane < 8) ? red[lane] : 0.0f;
#pragma unroll
        for (int o = 4; o; o >>= 1) t += __shfl_xor_sync(0xffffffffu, t, o);
        if (lane == 0) s_sum = t;
    }
    __syncthreads();
    if (tid < L_) g_attn[b * L_ + tid] = e / s_sum;
}

// ---------------------------------------------------------------------------
// Kernel 4: ctx partials. grid (7 l-chunks, 32 b), block 128.
// Thread owns float4 of s; 28 l iterations.
// ---------------------------------------------------------------------------
__global__ __launch_bounds__(128) void ctx_part(const float* __restrict__ xs) {
    int b = blockIdx.y;
    int lc = blockIdx.x;
    int l0 = lc * LPC;
    int tid = threadIdx.x;
    __shared__ float sattn[LPC];
    if (tid < LPC) sattn[tid] = g_attn[b * L_ + l0 + tid];
    __syncthreads();

    const float4* Xp = (const float4*)(xs + (size_t)b * L_ * S_ + (size_t)l0 * S_) + tid;
    float4 acc = {0.0f, 0.0f, 0.0f, 0.0f};
#pragma unroll 4
    for (int l = 0; l < LPC; l++) {
        float w = sattn[l];
        float4 v = Xp[l * (S_ / 4)];
        acc.x += w * v.x;
        acc.y += w * v.y;
        acc.z += w * v.z;
        acc.w += w * v.w;
    }
    *(float4*)&g_ctxpart[lc][b][tid * 4] = acc;
}

// ---------------------------------------------------------------------------
// Kernel 5: reduce partials -> tf32 compact ctx. grid 32, block 128.
// ---------------------------------------------------------------------------
__global__ __launch_bounds__(128) void ctx_reduce() {
    int b = blockIdx.x;
    int tid = threadIdx.x;
    float4 acc = {0.0f, 0.0f, 0.0f, 0.0f};
#pragma unroll
    for (int lc = 0; lc < LCH; lc++) {
        float4 v = *(const float4*)&g_ctxpart[lc][b][tid * 4];
        acc.x += v.x;
        acc.y += v.y;
        acc.z += v.z;
        acc.w += v.w;
    }
    uint4 u;
    u.x = f2tf32(acc.x);
    u.y = f2tf32(acc.y);
    u.z = f2tf32(acc.z);
    u.w = f2tf32(acc.w);
    *(uint4*)(g_ctx32 + b * S_ + tid * 4) = u;
}

// ---------------------------------------------------------------------------
// Kernel 6: TF32 MMA GEMM. out[m,n] = sum_k A[m,k]*W332[k,n] + b3[n]
// A[m, k<512] = g_Ax32[m]; A[m, k>=512] = g_ctx32[m>>5] (broadcast via L2).
// M=1024, N=512, K=1024. BM=64, BN=64, BK=32, 128 threads, double buffer.
// ---------------------------------------------------------------------------
#define GBM 64
#define GBN 64
#define GBK 32

__global__ __launch_bounds__(128) void gemm_tc(const float* __restrict__ b3,
                                               float* __restrict__ out) {
    __shared__ uint32_t As[2][GBM][36];
    __shared__ uint32_t Bs[2][GBK][72];

    int tid = threadIdx.x;
    int w = tid >> 5, lane = tid & 31;
    int m0 = blockIdx.y * GBM, n0 = blockIdx.x * GBN;
    int m_warp = (w & 1) * 32;
    int n_warp = (w >> 1) * 32;
    int r = lane >> 2;
    int c = lane & 3;

    float d[2][4][4];
#pragma unroll
    for (int f = 0; f < 2; f++)
#pragma unroll
        for (int g = 0; g < 4; g++)
#pragma unroll
            for (int i = 0; i < 4; i++) d[f][g][i] = 0.0f;

    int arow[4], ac4[4], bk[4], bn4[4];
#pragma unroll
    for (int it = 0; it < 4; it++) {
        int slot = tid + it * 128;
        arow[it] = slot >> 3;
        ac4[it] = slot & 7;
        bk[it] = slot >> 4;
        bn4[it] = slot & 15;
    }

    auto issue_tile = [&](int k0, int buf) {
        if (k0 < 512) {
#pragma unroll
            for (int it = 0; it < 4; it++) {
                uint32_t dst =
                    (uint32_t)__cvta_generic_to_shared(&As[buf][arow[it]][ac4[it] * 4]);
                cp_async16(dst, g_Ax32 + (size_t)(m0 + arow[it]) * D_ + k0 + ac4[it] * 4);
            }
        } else {
#pragma unroll
            for (int it = 0; it < 4; it++) {
                uint32_t dst =
                    (uint32_t)__cvta_generic_to_shared(&As[buf][arow[it]][ac4[it] * 4]);
                cp_async16(dst, g_ctx32 + (size_t)((m0 + arow[it]) >> 5) * S_ +
                                    (k0 - 512) + ac4[it] * 4);
            }
        }
#pragma unroll
        for (int it = 0; it < 4; it++) {
            uint32_t dst =
                (uint32_t)__cvta_generic_to_shared(&Bs[buf][bk[it]][bn4[it] * 4]);
            cp_async16(dst, g_W332 + (size_t)(k0 + bk[it]) * D_ + n0 + bn4[it] * 4);
        }
        cp_commit();
    };

    issue_tile(0, 0);

    for (int t = 0; t < KTOT / GBK; t++) {
        int buf = t & 1;
        if (t + 1 < KTOT / GBK) {
            issue_tile((t + 1) * GBK, buf ^ 1);
            cp_wait<1>();
        } else {
            cp_wait<0>();
        }
        __syncthreads();

#pragma unroll
        for (int kk8 = 0; kk8 < 4; kk8++) {
            int kb = kk8 * 8;
            uint32_t a[2][4];
#pragma unroll
            for (int f = 0; f < 2; f++) {
                int mrow = m_warp + f * 16 + r;
                a[f][0] = As[buf][mrow][kb + c];
                a[f][1] = As[buf][mrow + 8][kb + c];
                a[f][2] = As[buf][mrow][kb + c + 4];
                a[f][3] = As[buf][mrow + 8][kb + c + 4];
            }
#pragma unroll
            for (int g = 0; g < 4; g++) {
                int ncol = n_warp + g * 8 + r;
                uint32_t b0 = Bs[buf][kb + c][ncol];
                uint32_t b1 = Bs[buf][kb + c + 4][ncol];
#pragma unroll
                for (int f = 0; f < 2; f++) {
                    asm volatile(
                        "mma.sync.aligned.m16n8k8.row.col.f32.tf32.tf32.f32 "
                        "{%0,%1,%2,%3}, {%4,%5,%6,%7}, {%8,%9}, {%0,%1,%2,%3};\n"
                        : "+f"(d[f][g][0]), "+f"(d[f][g][1]), "+f"(d[f][g][2]),
                          "+f"(d[f][g][3])
                        : "r"(a[f][0]), "r"(a[f][1]), "r"(a[f][2]), "r"(a[f][3]),
                          "r"(b0), "r"(b1));
                }
            }
        }
        __syncthreads();
    }

    int c2 = c * 2;
#pragma unroll
    for (int g = 0; g < 4; g++) {
        int n = n0 + n_warp + g * 8 + c2;
        float2 bias = *(const float2*)(b3 + n);
#pragma unroll
        for (int f = 0; f < 2; f++) {
            int m = m0 + m_warp + f * 16 + r;
            float2 o0, o1;
            o0.x = d[f][g][0] + bias.x;
            o0.y = d[f][g][1] + bias.y;
            o1.x = d[f][g][2] + bias.x;
            o1.y = d[f][g][3] + bias.y;
            *(float2*)(out + (size_t)m * D_ + n) = o0;
            *(float2*)(out + (size_t)(m + 8) * D_ + n) = o1;
        }
    }
}

extern "C" void kernel_launch(void* const* d_in, const int* in_sizes, int n_in,
                              void* d_out, int out_size) {
    const float* x  = (const float*)d_in[0];   // [32,32,512]
    const float* xs = (const float*)d_in[1];   // [32,196,512]
    const float* W1 = (const float*)d_in[3];   // [512,512]
    const float* W3 = (const float*)d_in[5];   // [1024,512]
    const float* b3 = (const float*)d_in[7];   // [512]
    const float* V  = (const float*)d_in[8];   // [512,1]
    float* out = (float*)d_out;                // [32,32,512]

    prep_convert<<<256, 256>>>(x, W3);
    w1v_kernel<<<64, 256>>>(W1, V);
    scores_kernel<<<dim3(LCH, B_), 256>>>(xs);
    softmax_kernel<<<B_, 256>>>();
    ctx_part<<<dim3(LCH, B_), 128>>>(xs);
    ctx_reduce<<<B_, 128>>>();
    gemm_tc<<<dim3(D_ / GBN, M_ / GBM), 128>>>(b3, out);
}

// round 11
// speedup vs baseline: 1.6875x; 1.1272x over previous
#include <cuda_runtime.h>
#include <cuda_bf16.h>
#include <cstdint>

// Problem: B=32, T=32, L=196, S=512, D=512
// Math reduction: softmax is shift-invariant => attention independent of h,t.
//   attn[b,:]  = softmax_l( x_static[b] @ (W1@V) )
//   ctx[b,:]   = attn[b,:] @ x_static[b]
//   out[b,t,:] = concat(x[b,t,:], ctx[b,:]) @ W3 + b3   (K=1024 TF32 MMA GEMM)
//
// 4 launches: prep_fused -> scores -> ctx_fused (softmax + partial + last-block
// reduce) -> gemm_tc. Launch-count is the binding constraint at this scale.

#define D_ 512
#define S_ 512
#define L_ 196
#define B_ 32
#define T_ 32
#define KTOT 1024
#define M_ 1024
#define LCH 7
#define LPC 28

__device__ float g_w1v[S_];
__device__ float g_scores[B_ * L_];
__device__ float g_ctxpart[LCH][B_][S_];
__device__ unsigned int g_ctx_cnt[B_];
__device__ uint32_t g_Ax32[M_ * D_];     // tf32 x
__device__ uint32_t g_ctx32[B_ * S_];    // tf32 ctx (compact)
__device__ uint32_t g_W332[KTOT * D_];   // tf32 W3

__device__ __forceinline__ uint32_t f2tf32(float f) {
    uint32_t u;
    asm("cvt.rna.tf32.f32 %0, %1;" : "=r"(u) : "f"(f));
    return u;
}
__device__ __forceinline__ void cp_async16(uint32_t smem_addr, const void* gptr) {
    asm volatile("cp.async.cg.shared.global [%0], [%1], 16;\n" ::"r"(smem_addr),
                 "l"(gptr));
}
__device__ __forceinline__ void cp_commit() {
    asm volatile("cp.async.commit_group;\n");
}
template <int N>
__device__ __forceinline__ void cp_wait() {
    asm volatile("cp.async.wait_group %0;\n" ::"n"(N));
}

// ---------------------------------------------------------------------------
// Kernel 1 (fused prep): x->tf32, W3->tf32, w1v = W1@V, counter reset.
// 256 blocks x 256 threads.
// ---------------------------------------------------------------------------
__global__ __launch_bounds__(256) void prep_fused(const float* __restrict__ x,
                                                  const float* __restrict__ W3,
                                                  const float* __restrict__ W1,
                                                  const float* __restrict__ V) {
    int gtid = blockIdx.x * 256 + threadIdx.x;  // 65536 threads

    if (blockIdx.x == 0 && threadIdx.x < B_) g_ctx_cnt[threadIdx.x] = 0u;

    // x: 131072 float4 slots, 2 per thread
#pragma unroll
    for (int it = 0; it < 2; it++) {
        int j = (gtid + it * 65536) * 4;
        float4 v = *(const float4*)(x + j);
        uint4 u;
        u.x = f2tf32(v.x);
        u.y = f2tf32(v.y);
        u.z = f2tf32(v.z);
        u.w = f2tf32(v.w);
        *(uint4*)(g_Ax32 + j) = u;
    }
    // W3: 131072 float4 slots, 2 per thread
#pragma unroll
    for (int it = 0; it < 2; it++) {
        int j = (gtid + it * 65536) * 4;
        float4 v = *(const float4*)(W3 + j);
        uint4 u;
        u.x = f2tf32(v.x);
        u.y = f2tf32(v.y);
        u.z = f2tf32(v.z);
        u.w = f2tf32(v.w);
        *(uint4*)(g_W332 + j) = u;
    }

    // w1v: first 512 warps, warp per row
    int gwarp = gtid >> 5;
    int lane = threadIdx.x & 31;
    if (gwarp < S_) {
        const float4* row = (const float4*)(W1 + (size_t)gwarp * D_);
        const float4* v4 = (const float4*)V;
        float acc = 0.0f;
#pragma unroll
        for (int i = 0; i < 4; i++) {
            int idx = lane + i * 32;
            float4 a = row[idx];
            float4 b = v4[idx];
            acc += a.x * b.x + a.y * b.y + a.z * b.z + a.w * b.w;
        }
#pragma unroll
        for (int o = 16; o; o >>= 1) acc += __shfl_xor_sync(0xffffffffu, acc, o);
        if (lane == 0) g_w1v[gwarp] = acc;
    }
}

// ---------------------------------------------------------------------------
// Kernel 2: scores[b,l] = dot(x_static[b,l,:], w1v). grid (7, 32), warp/row.
// ---------------------------------------------------------------------------
__global__ __launch_bounds__(256) void scores_kernel(const float* __restrict__ xs) {
    int b = blockIdx.y;
    int l0 = blockIdx.x * LPC;
    __shared__ float sw1v[S_];
    int tid = threadIdx.x;
    if (tid < S_ / 4) ((float4*)sw1v)[tid] = ((const float4*)g_w1v)[tid];
    __syncthreads();

    int warp = tid >> 5, lane = tid & 31;
    const float* X = xs + (size_t)b * L_ * S_;
    for (int r = warp; r < LPC; r += 8) {
        int l = l0 + r;
        const float4* row = (const float4*)(X + (size_t)l * S_);
        const float4* w4 = (const float4*)sw1v;
        float acc = 0.0f;
#pragma unroll
        for (int i = 0; i < 4; i++) {
            int idx = lane + i * 32;
            float4 a = row[idx];
            float4 w = w4[idx];
            acc += a.x * w.x + a.y * w.y + a.z * w.z + a.w * w.w;
        }
#pragma unroll
        for (int o = 16; o; o >>= 1) acc += __shfl_xor_sync(0xffffffffu, acc, o);
        if (lane == 0) g_scores[b * L_ + l] = acc;
    }
}

// ---------------------------------------------------------------------------
// Kernel 3 (fused): per-block softmax recompute + ctx partial + last-block
// reduce -> tf32 compact ctx. grid (7 l-chunks, 32 b), block 128.
// ---------------------------------------------------------------------------
__global__ __launch_bounds__(128) void ctx_fused(const float* __restrict__ xs) {
    int b = blockIdx.y;
    int lc = blockIdx.x;
    int l0 = lc * LPC;
    int tid = threadIdx.x;
    int warp = tid >> 5, lane = tid & 31;

    __shared__ float ssc[256];
    __shared__ float red[4];
    __shared__ float s_max, s_sum;
    __shared__ unsigned int s_last;
    __shared__ float sattn[LPC];

    // load all 196 scores (L2-hot)
    float v0 = g_scores[b * L_ + tid];
    float v1 = (tid + 128 < L_) ? g_scores[b * L_ + tid + 128] : -1e30f;
    ssc[tid] = v0;
    ssc[tid + 128] = v1;

    // block max
    float m = fmaxf(v0, v1);
#pragma unroll
    for (int o = 16; o; o >>= 1) m = fmaxf(m, __shfl_xor_sync(0xffffffffu, m, o));
    if (lane == 0) red[warp] = m;
    __syncthreads();
    if (tid == 0) s_max = fmaxf(fmaxf(red[0], red[1]), fmaxf(red[2], red[3]));
    __syncthreads();
    float mx = s_max;

    // exp-sum
    float e0 = __expf(v0 - mx);
    float e1 = (tid + 128 < L_) ? __expf(v1 - mx) : 0.0f;
    float ps = e0 + e1;
#pragma unroll
    for (int o = 16; o; o >>= 1) ps += __shfl_xor_sync(0xffffffffu, ps, o);
    if (lane == 0) red[warp] = ps;
    __syncthreads();
    if (tid == 0) s_sum = red[0] + red[1] + red[2] + red[3];
    __syncthreads();
    float inv = 1.0f / s_sum;

    if (tid < LPC) sattn[tid] = __expf(ssc[l0 + tid] - mx) * inv;
    __syncthreads();

    // partial ctx over this chunk's 28 rows; thread owns one float4 of s
    const float4* Xp = (const float4*)(xs + (size_t)b * L_ * S_ + (size_t)l0 * S_) + tid;
    float4 acc = {0.0f, 0.0f, 0.0f, 0.0f};
#pragma unroll 4
    for (int l = 0; l < LPC; l++) {
        float w = sattn[l];
        float4 v = Xp[l * (S_ / 4)];
        acc.x += w * v.x;
        acc.y += w * v.y;
        acc.z += w * v.z;
        acc.w += w * v.w;
    }
    *(float4*)&g_ctxpart[lc][b][tid * 4] = acc;

    // last-block-per-batch reduction
    __threadfence();
    __syncthreads();
    if (tid == 0) s_last = atomicAdd(&g_ctx_cnt[b], 1u);
    __syncthreads();
    if (s_last == LCH - 1) {
        float4 t = {0.0f, 0.0f, 0.0f, 0.0f};
#pragma unroll
        for (int k = 0; k < LCH; k++) {
            float4 p = *(const float4*)&g_ctxpart[k][b][tid * 4];
            t.x += p.x;
            t.y += p.y;
            t.z += p.z;
            t.w += p.w;
        }
        uint4 u;
        u.x = f2tf32(t.x);
        u.y = f2tf32(t.y);
        u.z = f2tf32(t.z);
        u.w = f2tf32(t.w);
        *(uint4*)(g_ctx32 + b * S_ + tid * 4) = u;
    }
}

// ---------------------------------------------------------------------------
// Kernel 4: TF32 MMA GEMM. out[m,n] = sum_k A[m,k]*W332[k,n] + b3[n]
// A[m, k<512] = g_Ax32[m]; A[m, k>=512] = g_ctx32[m>>5] (broadcast via L2).
// M=1024, N=512, K=1024. BM=64, BN=64, BK=32, 128 threads, double buffer.
// ---------------------------------------------------------------------------
#define GBM 64
#define GBN 64
#define GBK 32

__global__ __launch_bounds__(128) void gemm_tc(const float* __restrict__ b3,
                                               float* __restrict__ out) {
    __shared__ uint32_t As[2][GBM][36];
    __shared__ uint32_t Bs[2][GBK][72];

    int tid = threadIdx.x;
    int w = tid >> 5, lane = tid & 31;
    int m0 = blockIdx.y * GBM, n0 = blockIdx.x * GBN;
    int m_warp = (w & 1) * 32;
    int n_warp = (w >> 1) * 32;
    int r = lane >> 2;
    int c = lane & 3;

    float d[2][4][4];
#pragma unroll
    for (int f = 0; f < 2; f++)
#pragma unroll
        for (int g = 0; g < 4; g++)
#pragma unroll
            for (int i = 0; i < 4; i++) d[f][g][i] = 0.0f;

    int arow[4], ac4[4], bk[4], bn4[4];
#pragma unroll
    for (int it = 0; it < 4; it++) {
        int slot = tid + it * 128;
        arow[it] = slot >> 3;
        ac4[it] = slot & 7;
        bk[it] = slot >> 4;
        bn4[it] = slot & 15;
    }

    auto issue_tile = [&](int k0, int buf) {
        if (k0 < 512) {
#pragma unroll
            for (int it = 0; it < 4; it++) {
                uint32_t dst =
                    (uint32_t)__cvta_generic_to_shared(&As[buf][arow[it]][ac4[it] * 4]);
                cp_async16(dst, g_Ax32 + (size_t)(m0 + arow[it]) * D_ + k0 + ac4[it] * 4);
            }
        } else {
#pragma unroll
            for (int it = 0; it < 4; it++) {
                uint32_t dst =
                    (uint32_t)__cvta_generic_to_shared(&As[buf][arow[it]][ac4[it] * 4]);
                cp_async16(dst, g_ctx32 + (size_t)((m0 + arow[it]) >> 5) * S_ +
                                    (k0 - 512) + ac4[it] * 4);
            }
        }
#pragma unroll
        for (int it = 0; it < 4; it++) {
            uint32_t dst =
                (uint32_t)__cvta_generic_to_shared(&Bs[buf][bk[it]][bn4[it] * 4]);
            cp_async16(dst, g_W332 + (size_t)(k0 + bk[it]) * D_ + n0 + bn4[it] * 4);
        }
        cp_commit();
    };

    issue_tile(0, 0);

    for (int t = 0; t < KTOT / GBK; t++) {
        int buf = t & 1;
        if (t + 1 < KTOT / GBK) {
            issue_tile((t + 1) * GBK, buf ^ 1);
            cp_wait<1>();
        } else {
            cp_wait<0>();
        }
        __syncthreads();

#pragma unroll
        for (int kk8 = 0; kk8 < 4; kk8++) {
            int kb = kk8 * 8;
            uint32_t a[2][4];
#pragma unroll
            for (int f = 0; f < 2; f++) {
                int mrow = m_warp + f * 16 + r;
                a[f][0] = As[buf][mrow][kb + c];
                a[f][1] = As[buf][mrow + 8][kb + c];
                a[f][2] = As[buf][mrow][kb + c + 4];
                a[f][3] = As[buf][mrow + 8][kb + c + 4];
            }
#pragma unroll
            for (int g = 0; g < 4; g++) {
                int ncol = n_warp + g * 8 + r;
                uint32_t b0 = Bs[buf][kb + c][ncol];
                uint32_t b1 = Bs[buf][kb + c + 4][ncol];
#pragma unroll
                for (int f = 0; f < 2; f++) {
                    asm volatile(
                        "mma.sync.aligned.m16n8k8.row.col.f32.tf32.tf32.f32 "
                        "{%0,%1,%2,%3}, {%4,%5,%6,%7}, {%8,%9}, {%0,%1,%2,%3};\n"
                        : "+f"(d[f][g][0]), "+f"(d[f][g][1]), "+f"(d[f][g][2]),
                          "+f"(d[f][g][3])
                        : "r"(a[f][0]), "r"(a[f][1]), "r"(a[f][2]), "r"(a[f][3]),
                          "r"(b0), "r"(b1));
                }
            }
        }
        __syncthreads();
    }

    int c2 = c * 2;
#pragma unroll
    for (int g = 0; g < 4; g++) {
        int n = n0 + n_warp + g * 8 + c2;
        float2 bias = *(const float2*)(b3 + n);
#pragma unroll
        for (int f = 0; f < 2; f++) {
            int m = m0 + m_warp + f * 16 + r;
            float2 o0, o1;
            o0.x = d[f][g][0] + bias.x;
            o0.y = d[f][g][1] + bias.y;
            o1.x = d[f][g][2] + bias.x;
            o1.y = d[f][g][3] + bias.y;
            *(float2*)(out + (size_t)m * D_ + n) = o0;
            *(float2*)(out + (size_t)(m + 8) * D_ + n) = o1;
        }
    }
}

extern "C" void kernel_launch(void* const* d_in, const int* in_sizes, int n_in,
                              void* d_out, int out_size) {
    const float* x  = (const float*)d_in[0];   // [32,32,512]
    const float* xs = (const float*)d_in[1];   // [32,196,512]
    const float* W1 = (const float*)d_in[3];   // [512,512]
    const float* W3 = (const float*)d_in[5];   // [1024,512]
    const float* b3 = (const float*)d_in[7];   // [512]
    const float* V  = (const float*)d_in[8];   // [512,1]
    float* out = (float*)d_out;                // [32,32,512]

    prep_fused<<<256, 256>>>(x, W3, W1, V);
    scores_kernel<<<dim3(LCH, B_), 256>>>(xs);
    ctx_fused<<<dim3(LCH, B_), 128>>>(xs);
    gemm_tc<<<dim3(D_ / GBN, M_ / GBM), 128>>>(b3, out);
}